// round 1
// baseline (speedup 1.0000x reference)
#include <cuda_runtime.h>

#define NS 128    // sources (== threads per block)
#define NP 2048   // points per mirror
#define NM 64     // mirrors
#define NCYL 16
#define NBOX 8
#define IH 512
#define IW 512
#define EXT 12.0f
#define EPSF 1e-9f

__device__ __forceinline__ float sqrt_approx(float x) {
    float r; asm("sqrt.approx.f32 %0, %1;" : "=f"(r) : "f"(x)); return r;
}
__device__ __forceinline__ float rcp_approx(float x) {
    float r; asm("rcp.approx.f32 %0, %1;" : "=f"(r) : "f"(x)); return r;
}
// ~1-ulp reciprocal: approx + one Newton step
__device__ __forceinline__ float rcp_refined(float x) {
    float r = rcp_approx(x);
    r = r * (2.0f - x * r);
    return r;
}
// ~1-ulp rsqrt: approx + one Newton step
__device__ __forceinline__ float rsqrt_refined(float x) {
    float r = rsqrtf(x);
    r = r * fmaf(-0.5f * x * r, r, 1.5f);
    return r;
}

__global__ void zero_kernel(float* __restrict__ out, int n) {
    int i = blockIdx.x * blockDim.x + threadIdx.x;
    if (i < n) out[i] = 0.0f;
}

__global__ __launch_bounds__(NS) void render_kernel(
    const float* __restrict__ sources,     // [NS,3]
    const float* __restrict__ mpoints,     // [NM,NP,3]
    const float* __restrict__ mnormals,    // [NM,NP,3]
    const float* __restrict__ mpos,        // [NM,3]
    const float* __restrict__ mrot,        // [NM,3,3]
    const float* __restrict__ cp1,         // [NCYL,3]
    const float* __restrict__ cp2,         // [NCYL,3]
    const float* __restrict__ crad,        // [NCYL]
    const float* __restrict__ bp1,         // [NBOX,3]
    const float* __restrict__ bp2,         // [NBOX,3]
    const float* __restrict__ spos,        // [3]
    const float* __restrict__ snorm,       // [3]
    float* __restrict__ out)               // [IH,IW]
{
    const int pid = blockIdx.x;        // 0 .. NM*NP-1
    const int m   = pid >> 11;         // / NP
    const int p   = pid & (NP - 1);
    const int tid = threadIdx.x;

    // ---- per-block (mirror point) transform: every thread computes it
    // (broadcast loads, ~30 flops; avoids an extra sync) ----
    const float* R  = mrot + m * 9;
    const float* pt = mpoints  + (m * NP + p) * 3;
    const float* nm = mnormals + (m * NP + p) * 3;
    float px = pt[0], py = pt[1], pz = pt[2];
    float vx = nm[0], vy = nm[1], vz = nm[2];
    float r00 = R[0], r01 = R[1], r02 = R[2];
    float r10 = R[3], r11 = R[4], r12 = R[5];
    float r20 = R[6], r21 = R[7], r22 = R[8];
    float tpx = fmaf(r00, px, fmaf(r01, py, r02 * pz)) + mpos[m * 3 + 0];
    float tpy = fmaf(r10, px, fmaf(r11, py, r12 * pz)) + mpos[m * 3 + 1];
    float tpz = fmaf(r20, px, fmaf(r21, py, r22 * pz)) + mpos[m * 3 + 2];
    float tnx = fmaf(r00, vx, fmaf(r01, vy, r02 * vz));
    float tny = fmaf(r10, vx, fmaf(r11, vy, r12 * vz));
    float tnz = fmaf(r20, vx, fmaf(r21, vy, r22 * vz));

    // ---- ray-independent precompute into shared ----
    // cylinders: axis a, perpendicular offset mvec = oc - (oc.a)a, oa, C, L
    __shared__ float sca[NCYL][4];   // ax, ay, az, L
    __shared__ float scm[NCYL][4];   // mx, my, mz, oa
    __shared__ float scC[NCYL];      // m.m - r^2
    __shared__ float sb1[NBOX][3];   // p1 - o
    __shared__ float sb2[NBOX][3];   // p2 - o

    if (tid < NCYL) {
        int c = tid;
        float a0 = cp2[3*c+0] - cp1[3*c+0];
        float a1 = cp2[3*c+1] - cp1[3*c+1];
        float a2 = cp2[3*c+2] - cp1[3*c+2];
        float L  = sqrtf(a0*a0 + a1*a1 + a2*a2);
        float il = 1.0f / (L + EPSF);
        a0 *= il; a1 *= il; a2 *= il;
        float oc0 = tpx - cp1[3*c+0];
        float oc1 = tpy - cp1[3*c+1];
        float oc2 = tpz - cp1[3*c+2];
        float oa  = oc0*a0 + oc1*a1 + oc2*a2;
        float m0  = fmaf(-oa, a0, oc0);
        float m1  = fmaf(-oa, a1, oc1);
        float m2  = fmaf(-oa, a2, oc2);
        float r   = crad[c];
        sca[c][0] = a0; sca[c][1] = a1; sca[c][2] = a2; sca[c][3] = L;
        scm[c][0] = m0; scm[c][1] = m1; scm[c][2] = m2; scm[c][3] = oa;
        scC[c]    = fmaf(m0, m0, fmaf(m1, m1, m2*m2)) - r*r;
    } else if (tid < NCYL + NBOX) {
        int b = tid - NCYL;
        sb1[b][0] = bp1[3*b+0] - tpx;
        sb1[b][1] = bp1[3*b+1] - tpy;
        sb1[b][2] = bp1[3*b+2] - tpz;
        sb2[b][0] = bp2[3*b+0] - tpx;
        sb2[b][1] = bp2[3*b+1] - tpy;
        sb2[b][2] = bp2[3*b+2] - tpz;
    }
    __syncthreads();

    // ---- per-thread ray ----
    float sx = sources[tid*3+0], sy = sources[tid*3+1], sz = sources[tid*3+2];
    float dx0 = tpx - sx, dy0 = tpy - sy, dz0 = tpz - sz;
    float len2 = fmaf(dx0, dx0, fmaf(dy0, dy0, dz0*dz0));
    float il = rsqrt_refined(len2);
    float dx = dx0 * il, dy = dy0 * il, dz = dz0 * il;
    float ux = -dx, uy = -dy, uz = -dz;   // occlusion ray: mirror -> source

    bool blocked = false;

    // cylinders: A = 1 - (u.a)^2, B/2 = m.u, disc' = (B/2)^2 - A*C  (disc = 4*disc')
    #pragma unroll
    for (int c = 0; c < NCYL; c++) {
        float ua = fmaf(ux, sca[c][0], fmaf(uy, sca[c][1], uz * sca[c][2]));
        float hB = fmaf(ux, scm[c][0], fmaf(uy, scm[c][1], uz * scm[c][2]));
        float A  = fmaf(-ua, ua, 1.0f);
        float dp = fmaf(hB, hB, -A * scC[c]);
        if (dp > 0.0f) {
            float sq  = sqrt_approx(dp);
            float inv = __fdividef(1.0f, fmaf(2.0f, A, EPSF));
            float t1  = (-2.0f * hB - 2.0f * sq) * inv;
            float t2  = (-2.0f * hB + 2.0f * sq) * inv;
            float oa  = scm[c][3];
            float L   = sca[c][3];
            float x1  = fmaf(t1, ua, oa);
            float x2  = fmaf(t2, ua, oa);
            bool h1 = (t1 > EPSF) & (x1 >= 0.0f) & (x1 <= L);
            bool h2 = (t2 > EPSF) & (x2 >= 0.0f) & (x2 <= L);
            if (h1 | h2) { blocked = true; break; }
        }
    }

    if (!blocked) {
        float aux = (fabsf(ux) < EPSF) ? EPSF : ux;
        float auy = (fabsf(uy) < EPSF) ? EPSF : uy;
        float auz = (fabsf(uz) < EPSF) ? EPSF : uz;
        float ivx = __fdividef(1.0f, aux);
        float ivy = __fdividef(1.0f, auy);
        float ivz = __fdividef(1.0f, auz);
        #pragma unroll
        for (int b = 0; b < NBOX; b++) {
            float lx = sb1[b][0] * ivx, hx = sb2[b][0] * ivx;
            float ly = sb1[b][1] * ivy, hy = sb2[b][1] * ivy;
            float lz = sb1[b][2] * ivz, hz = sb2[b][2] * ivz;
            float nx_ = fminf(lx, hx), xx_ = fmaxf(lx, hx);
            float ny_ = fminf(ly, hy), xy_ = fmaxf(ly, hy);
            float nz_ = fminf(lz, hz), xz_ = fmaxf(lz, hz);
            float tmin = fmaxf(fmaxf(nx_, ny_), nz_);
            float tmax = fminf(fminf(xx_, xy_), xz_);
            if (tmax >= fmaxf(tmin, EPSF)) { blocked = true; break; }
        }
    }

    if (!blocked) {
        float dn   = fmaf(dx, tnx, fmaf(dy, tny, dz * tnz));
        float rx   = fmaf(-2.0f * dn, tnx, dx);
        float ry   = fmaf(-2.0f * dn, tny, dy);
        float rz   = fmaf(-2.0f * dn, tnz, dz);
        float cosv = fabsf(dn);
        float Nx = snorm[0], Ny = snorm[1], Nz = snorm[2];
        float denom = fmaf(rx, Nx, fmaf(ry, Ny, rz * Nz)) + EPSF;
        float tnum  = fmaf(spos[0] - tpx, Nx,
                      fmaf(spos[1] - tpy, Ny, (spos[2] - tpz) * Nz));
        float t  = tnum * rcp_refined(denom);
        float qx = fmaf(t, rx, tpx);
        float qy = fmaf(t, ry, tpy);
        float fx = (qx + EXT) * (1.0f / (2.0f * EXT)) * (float)IW;
        float fy = (qy + EXT) * (1.0f / (2.0f * EXT)) * (float)IH;
        float flx = floorf(fx), fly = floorf(fy);
        // bounds check in float domain: inf/NaN safely rejected
        if (flx >= 0.0f && flx < (float)IW && fly >= 0.0f && fly < (float)IH) {
            int ix = (int)flx;
            int iy = (int)fly;
            atomicAdd(out + iy * IW + ix, cosv);
        }
    }
}

extern "C" void kernel_launch(void* const* d_in, const int* in_sizes, int n_in,
                              void* d_out, int out_size) {
    float* out = (float*)d_out;
    zero_kernel<<<(out_size + 511) / 512, 512>>>(out, out_size);
    render_kernel<<<NM * NP, NS>>>(
        (const float*)d_in[0],   // sources
        (const float*)d_in[1],   // mirror_points
        (const float*)d_in[2],   // mirror_normals
        (const float*)d_in[3],   // mirror_positions
        (const float*)d_in[4],   // mirror_rotations
        (const float*)d_in[5],   // cyl_p1
        (const float*)d_in[6],   // cyl_p2
        (const float*)d_in[7],   // cyl_radius
        (const float*)d_in[8],   // box_p1
        (const float*)d_in[9],   // box_p2
        (const float*)d_in[10],  // sensor_plane_pos
        (const float*)d_in[11],  // sensor_plane_normal
        out);
}

// round 2
// speedup vs baseline: 2.5305x; 2.5305x over previous
#include <cuda_runtime.h>

#define NS 128    // sources (== threads per block)
#define NP 2048   // points per mirror
#define NM 64     // mirrors
#define NCYL 16
#define NBOX 8
#define IH 512
#define IW 512
#define EXT 12.0f
#define EPSF 1e-9f
#define MARG 0.02f

__device__ float4 g_sb1;   // sxmin, sxmax, symin, symax
__device__ float2 g_sb2;   // szmin, szmax

__device__ __forceinline__ float sqrt_approx(float x) {
    float r; asm("sqrt.approx.f32 %0, %1;" : "=f"(r) : "f"(x)); return r;
}
__device__ __forceinline__ float rcp_approx(float x) {
    float r; asm("rcp.approx.f32 %0, %1;" : "=f"(r) : "f"(x)); return r;
}
__device__ __forceinline__ float rcp_refined(float x) {
    float r = rcp_approx(x);
    r = r * (2.0f - x * r);
    return r;
}
__device__ __forceinline__ float rsqrt_refined(float x) {
    float r = rsqrtf(x);
    r = r * fmaf(-0.5f * x * r, r, 1.5f);
    return r;
}

__global__ void zero_kernel(float4* __restrict__ out, int n4) {
    int i = blockIdx.x * blockDim.x + threadIdx.x;
    if (i < n4) out[i] = make_float4(0.f, 0.f, 0.f, 0.f);
}

// single warp: min/max bounds of sources
__global__ void bounds_kernel(const float* __restrict__ src) {
    int lane = threadIdx.x;
    float xmn = 1e30f, xmx = -1e30f, ymn = 1e30f, ymx = -1e30f;
    float zmn = 1e30f, zmx = -1e30f;
    for (int i = lane; i < NS; i += 32) {
        float x = src[3*i], y = src[3*i+1], z = src[3*i+2];
        xmn = fminf(xmn, x); xmx = fmaxf(xmx, x);
        ymn = fminf(ymn, y); ymx = fmaxf(ymx, y);
        zmn = fminf(zmn, z); zmx = fmaxf(zmx, z);
    }
    #pragma unroll
    for (int o = 16; o; o >>= 1) {
        xmn = fminf(xmn, __shfl_xor_sync(0xffffffffu, xmn, o));
        xmx = fmaxf(xmx, __shfl_xor_sync(0xffffffffu, xmx, o));
        ymn = fminf(ymn, __shfl_xor_sync(0xffffffffu, ymn, o));
        ymx = fmaxf(ymx, __shfl_xor_sync(0xffffffffu, ymx, o));
        zmn = fminf(zmn, __shfl_xor_sync(0xffffffffu, zmn, o));
        zmx = fmaxf(zmx, __shfl_xor_sync(0xffffffffu, zmx, o));
    }
    if (lane == 0) {
        g_sb1 = make_float4(xmn, xmx, ymn, ymx);
        g_sb2 = make_float2(zmn, zmx);
    }
}

__global__ __launch_bounds__(NS) void render_kernel(
    const float* __restrict__ sources,     // [NS,3]
    const float* __restrict__ mpoints,     // [NM,NP,3]
    const float* __restrict__ mnormals,    // [NM,NP,3]
    const float* __restrict__ mpos,        // [NM,3]
    const float* __restrict__ mrot,        // [NM,3,3]
    const float* __restrict__ cp1,         // [NCYL,3]
    const float* __restrict__ cp2,         // [NCYL,3]
    const float* __restrict__ crad,        // [NCYL]
    const float* __restrict__ bp1,         // [NBOX,3]
    const float* __restrict__ bp2,         // [NBOX,3]
    const float* __restrict__ spos,        // [3]
    const float* __restrict__ snorm,       // [3]
    float* __restrict__ out)               // [IH,IW]
{
    const int pid = blockIdx.x;
    const int m   = pid >> 11;
    const int p   = pid & (NP - 1);
    const int tid = threadIdx.x;

    // ---- per-block transform (all threads, broadcast loads) ----
    const float* R  = mrot + m * 9;
    const float* pt = mpoints  + (m * NP + p) * 3;
    const float* nv = mnormals + (m * NP + p) * 3;
    float px = pt[0], py = pt[1], pz = pt[2];
    float vx = nv[0], vy = nv[1], vz = nv[2];
    float r00 = R[0], r01 = R[1], r02 = R[2];
    float r10 = R[3], r11 = R[4], r12 = R[5];
    float r20 = R[6], r21 = R[7], r22 = R[8];
    float tpx = fmaf(r00, px, fmaf(r01, py, r02 * pz)) + mpos[m*3+0];
    float tpy = fmaf(r10, px, fmaf(r11, py, r12 * pz)) + mpos[m*3+1];
    float tpz = fmaf(r20, px, fmaf(r21, py, r22 * pz)) + mpos[m*3+2];
    float tnx = fmaf(r00, vx, fmaf(r01, vy, r02 * vz));
    float tny = fmaf(r10, vx, fmaf(r11, vy, r12 * vz));
    float tnz = fmaf(r20, vx, fmaf(r21, vy, r22 * vz));

    // ---- compacted obstacle lists ----
    __shared__ float4 s_cyl[NCYL];    // mx, my, C, idx
    __shared__ float2 s_cyl2[NCYL];   // oa, L
    __shared__ float4 s_b1[NBOX];     // bp1 - o
    __shared__ float4 s_b2[NBOX];     // bp2 - o
    __shared__ int    s_ncyl, s_nbox;

    if (tid < 32) {
        bool actC = false, actB = false;
        float4 cylA = make_float4(0,0,0,0); float2 cylB = make_float2(0,0);
        float4 bo1  = make_float4(0,0,0,0); float4 bo2 = make_float4(0,0,0,0);

        float4 sb = g_sb1;   // sx range, sy range
        float2 sz = g_sb2;   // sz range
        float dzl = sz.x - tpz, dzh = sz.y - tpz;
        bool degen = (dzl <= 0.01f);   // sources not clearly above: skip culling
        // conservative slope (w = (s.xy - o.xy)/(s.z - o.z)) bounds
        float nxl = sb.x - tpx, nxh = sb.y - tpx;
        float nyl = sb.z - tpy, nyh = sb.w - tpy;
        float wxl = fminf(nxl / dzl, nxl / dzh) - 1e-4f;
        float wxh = fmaxf(nxh / dzl, nxh / dzh) + 1e-4f;
        float wyl = fminf(nyl / dzl, nyl / dzh) - 1e-4f;
        float wyh = fmaxf(nyh / dzl, nyh / dzh) + 1e-4f;

        if (tid < NCYL) {
            int c = tid;
            float c1x = cp1[3*c+0], c1y = cp1[3*c+1], c1z = cp1[3*c+2];
            float c2z = cp2[3*c+2];
            float r   = crad[c];
            float mx = tpx - c1x, my = tpy - c1y;
            float zmax = fmaxf(c1z, c2z);
            float dmax = zmax - tpz + MARG;
            float Xl = tpx + dmax * fminf(wxl, 0.f);
            float Xh = tpx + dmax * fmaxf(wxh, 0.f);
            float Yl = tpy + dmax * fminf(wyl, 0.f);
            float Yh = tpy + dmax * fmaxf(wyh, 0.f);
            float ddx = fmaxf(fmaxf(c1x - Xh, Xl - c1x), 0.f);
            float ddy = fmaxf(fmaxf(c1y - Yh, Yl - c1y), 0.f);
            float rr = r + MARG;
            actC = degen | ((dmax > 0.f) & (fmaf(ddx, ddx, ddy*ddy) <= rr*rr));
            cylA = make_float4(mx, my, fmaf(mx,mx, my*my) - r*r, __int_as_float(c));
            float L = fabsf(c2z - c1z);   // vertical axis (exact in this dataset)
            cylB = make_float2(tpz - c1z, L);
        } else if (tid < NCYL + NBOX) {
            int b = tid - NCYL;
            float b1x = bp1[3*b+0], b1y = bp1[3*b+1], b1z = bp1[3*b+2];
            float b2x = bp2[3*b+0], b2y = bp2[3*b+1], b2z = bp2[3*b+2];
            float d2 = b2z - tpz + MARG;
            float Xl = tpx + d2 * fminf(wxl, 0.f);
            float Xh = tpx + d2 * fmaxf(wxh, 0.f);
            float Yl = tpy + d2 * fminf(wyl, 0.f);
            float Yh = tpy + d2 * fmaxf(wyh, 0.f);
            bool ovx = (Xh >= b1x - MARG) & (Xl <= b2x + MARG);
            bool ovy = (Yh >= b1y - MARG) & (Yl <= b2y + MARG);
            actB = degen | ((d2 > 0.f) & ovx & ovy);
            bo1 = make_float4(b1x - tpx, b1y - tpy, b1z - tpz, 0.f);
            bo2 = make_float4(b2x - tpx, b2y - tpy, b2z - tpz, 0.f);
        }
        unsigned mc = __ballot_sync(0xffffffffu, actC);
        unsigned mb = __ballot_sync(0xffffffffu, actB);
        unsigned lt = (1u << tid) - 1u;
        if (actC) { int pos = __popc(mc & lt); s_cyl[pos] = cylA; s_cyl2[pos] = cylB; }
        if (actB) { int pos = __popc(mb & lt) ; s_b1[pos] = bo1; s_b2[pos] = bo2; }
        if (tid == 0) { s_ncyl = __popc(mc); s_nbox = __popc(mb); }
    }
    __syncthreads();

    const int nc = s_ncyl;
    const int nb = s_nbox;

    // ---- per-thread ray ----
    float sx = sources[tid*3+0], sy = sources[tid*3+1], szv = sources[tid*3+2];
    float dx0 = tpx - sx, dy0 = tpy - sy, dz0 = tpz - szv;
    float len2 = fmaf(dx0, dx0, fmaf(dy0, dy0, dz0*dz0));
    float il = rsqrt_refined(len2);
    float dx = dx0 * il, dy = dy0 * il, dz = dz0 * il;
    float ux = -dx, uy = -dy, uz = -dz;   // occlusion ray dir

    float A = fmaf(ux, ux, uy*uy);        // 1 - (u.a)^2 with vertical axis
    bool blocked = false;

    for (int j = 0; j < nc; j++) {
        float4 v = s_cyl[j];
        float hB = fmaf(ux, v.x, uy * v.y);
        float dp = fmaf(hB, hB, -A * v.z);
        if (dp > 0.0f) {
            float2 w2 = s_cyl2[j];
            float sq  = sqrt_approx(dp);
            float inv = __fdividef(1.0f, fmaf(2.0f, A, EPSF));
            float t1  = (-2.0f * hB - 2.0f * sq) * inv;
            float t2  = (-2.0f * hB + 2.0f * sq) * inv;
            float x1  = fmaf(t1, uz, w2.x);
            float x2  = fmaf(t2, uz, w2.x);
            bool h1 = (t1 > EPSF) & (x1 >= 0.0f) & (x1 <= w2.y);
            bool h2 = (t2 > EPSF) & (x2 >= 0.0f) & (x2 <= w2.y);
            if (h1 | h2) { blocked = true; break; }
        }
    }

    if (!blocked && nb) {
        float aux = (fabsf(ux) < EPSF) ? EPSF : ux;
        float auy = (fabsf(uy) < EPSF) ? EPSF : uy;
        float auz = (fabsf(uz) < EPSF) ? EPSF : uz;
        float ivx = __fdividef(1.0f, aux);
        float ivy = __fdividef(1.0f, auy);
        float ivz = __fdividef(1.0f, auz);
        for (int b = 0; b < nb; b++) {
            float4 v1 = s_b1[b];
            float4 v2 = s_b2[b];
            float lx = v1.x * ivx, hx = v2.x * ivx;
            float ly = v1.y * ivy, hy = v2.y * ivy;
            float lz = v1.z * ivz, hz = v2.z * ivz;
            float nx_ = fminf(lx, hx), xx_ = fmaxf(lx, hx);
            float ny_ = fminf(ly, hy), xy_ = fmaxf(ly, hy);
            float nz_ = fminf(lz, hz), xz_ = fmaxf(lz, hz);
            float tmin = fmaxf(fmaxf(nx_, ny_), nz_);
            float tmax = fminf(fminf(xx_, xy_), xz_);
            if (tmax >= fmaxf(tmin, EPSF)) { blocked = true; break; }
        }
    }

    if (!blocked) {
        float dn   = fmaf(dx, tnx, fmaf(dy, tny, dz * tnz));
        float rx   = fmaf(-2.0f * dn, tnx, dx);
        float ry   = fmaf(-2.0f * dn, tny, dy);
        float rz   = fmaf(-2.0f * dn, tnz, dz);
        float cosv = fabsf(dn);
        float Nx = snorm[0], Ny = snorm[1], Nz = snorm[2];
        float denom = fmaf(rx, Nx, fmaf(ry, Ny, rz * Nz)) + EPSF;
        float tnum  = fmaf(spos[0] - tpx, Nx,
                      fmaf(spos[1] - tpy, Ny, (spos[2] - tpz) * Nz));
        float t  = tnum * rcp_refined(denom);
        float qx = fmaf(t, rx, tpx);
        float qy = fmaf(t, ry, tpy);
        float fx = (qx + EXT) * (1.0f / (2.0f * EXT)) * (float)IW;
        float fy = (qy + EXT) * (1.0f / (2.0f * EXT)) * (float)IH;
        float flx = floorf(fx), fly = floorf(fy);
        if (flx >= 0.0f && flx < (float)IW && fly >= 0.0f && fly < (float)IH) {
            int ix = (int)flx;
            int iy = (int)fly;
            atomicAdd(out + iy * IW + ix, cosv);
        }
    }
}

extern "C" void kernel_launch(void* const* d_in, const int* in_sizes, int n_in,
                              void* d_out, int out_size) {
    float* out = (float*)d_out;
    int n4 = out_size / 4;
    zero_kernel<<<(n4 + 255) / 256, 256>>>((float4*)out, n4);
    bounds_kernel<<<1, 32>>>((const float*)d_in[0]);
    render_kernel<<<NM * NP, NS>>>(
        (const float*)d_in[0],   // sources
        (const float*)d_in[1],   // mirror_points
        (const float*)d_in[2],   // mirror_normals
        (const float*)d_in[3],   // mirror_positions
        (const float*)d_in[4],   // mirror_rotations
        (const float*)d_in[5],   // cyl_p1
        (const float*)d_in[6],   // cyl_p2
        (const float*)d_in[7],   // cyl_radius
        (const float*)d_in[8],   // box_p1
        (const float*)d_in[9],   // box_p2
        (const float*)d_in[10],  // sensor_plane_pos
        (const float*)d_in[11],  // sensor_plane_normal
        out);
}

// round 3
// speedup vs baseline: 3.5254x; 1.3932x over previous
#include <cuda_runtime.h>

#define NS 128    // sources (== threads per block)
#define NP 2048   // points per mirror
#define NM 64     // mirrors
#define NPTS (NM*NP)
#define NCYL 16
#define NBOX 8
#define IH 512
#define IW 512
#define EXT 12.0f
#define EPSF 1e-9f
#define MARG 0.02f

// per-point scratch (written by prep_kernel, read by render_kernel)
__device__ float4 g_tp[NPTS];      // tpx, tpy, tpz, cull-mask (bits0-15 cyl, 16-23 box)
__device__ float4 g_tn[NPTS];      // tnx, tny, tnz, tnum
__device__ float4 g_cyl[NCYL];     // c1x, c1y, r^2, c1z
__device__ float  g_cylL[NCYL];    // axis length
__device__ float4 g_bx1[NBOX];     // box p1
__device__ float4 g_bx2[NBOX];     // box p2

__device__ __forceinline__ float sqrt_approx(float x) {
    float r; asm("sqrt.approx.f32 %0, %1;" : "=f"(r) : "f"(x)); return r;
}
__device__ __forceinline__ float rcp_approx(float x) {
    float r; asm("rcp.approx.f32 %0, %1;" : "=f"(r) : "f"(x)); return r;
}
__device__ __forceinline__ float rcp_refined(float x) {
    float r = rcp_approx(x);
    r = r * (2.0f - x * r);
    return r;
}
__device__ __forceinline__ float rsqrt_refined(float x) {
    float r = rsqrtf(x);
    r = r * fmaf(-0.5f * x * r, r, 1.5f);
    return r;
}

// One thread per mirror point. Also zero-fills the output image and builds
// the packed geometry tables.
__global__ __launch_bounds__(128) void prep_kernel(
    const float* __restrict__ src,
    const float* __restrict__ mpoints,
    const float* __restrict__ mnormals,
    const float* __restrict__ mpos,
    const float* __restrict__ mrot,
    const float* __restrict__ cp1,
    const float* __restrict__ cp2,
    const float* __restrict__ crad,
    const float* __restrict__ bp1,
    const float* __restrict__ bp2,
    const float* __restrict__ spos,
    const float* __restrict__ snorm,
    float4* __restrict__ out4)
{
    const int tid = threadIdx.x;
    const int pid = blockIdx.x * 128 + tid;

    // zero output image (65536 float4s; grid provides 131072 threads)
    if (pid < (IH * IW / 4)) out4[pid] = make_float4(0.f, 0.f, 0.f, 0.f);

    // geometry tables (block 0 only; used by render, NOT by the cull below)
    if (blockIdx.x == 0) {
        if (tid < NCYL) {
            float r = crad[tid];
            g_cyl[tid]  = make_float4(cp1[3*tid], cp1[3*tid+1], r * r, cp1[3*tid+2]);
            g_cylL[tid] = fabsf(cp2[3*tid+2] - cp1[3*tid+2]);
        } else if (tid < NCYL + NBOX) {
            int b = tid - NCYL;
            g_bx1[b] = make_float4(bp1[3*b], bp1[3*b+1], bp1[3*b+2], 0.f);
            g_bx2[b] = make_float4(bp2[3*b], bp2[3*b+1], bp2[3*b+2], 0.f);
        }
    }

    // ---- block-local source-bounds reduction (128 sources, one per thread) ----
    float x = src[tid*3], y = src[tid*3+1], z = src[tid*3+2];
    float xmn = x, xmx = x, ymn = y, ymx = y, zmn = z, zmx = z;
    #pragma unroll
    for (int o = 16; o; o >>= 1) {
        xmn = fminf(xmn, __shfl_xor_sync(0xffffffffu, xmn, o));
        xmx = fmaxf(xmx, __shfl_xor_sync(0xffffffffu, xmx, o));
        ymn = fminf(ymn, __shfl_xor_sync(0xffffffffu, ymn, o));
        ymx = fmaxf(ymx, __shfl_xor_sync(0xffffffffu, ymx, o));
        zmn = fminf(zmn, __shfl_xor_sync(0xffffffffu, zmn, o));
        zmx = fmaxf(zmx, __shfl_xor_sync(0xffffffffu, zmx, o));
    }
    __shared__ float sh[4][6];
    int w = tid >> 5;
    if ((tid & 31) == 0) {
        sh[w][0] = xmn; sh[w][1] = xmx; sh[w][2] = ymn;
        sh[w][3] = ymx; sh[w][4] = zmn; sh[w][5] = zmx;
    }
    __syncthreads();
    xmn = fminf(fminf(sh[0][0], sh[1][0]), fminf(sh[2][0], sh[3][0]));
    xmx = fmaxf(fmaxf(sh[0][1], sh[1][1]), fmaxf(sh[2][1], sh[3][1]));
    ymn = fminf(fminf(sh[0][2], sh[1][2]), fminf(sh[2][2], sh[3][2]));
    ymx = fmaxf(fmaxf(sh[0][3], sh[1][3]), fmaxf(sh[2][3], sh[3][3]));
    zmn = fminf(fminf(sh[0][4], sh[1][4]), fminf(sh[2][4], sh[3][4]));
    zmx = fmaxf(fmaxf(sh[0][5], sh[1][5]), fmaxf(sh[2][5], sh[3][5]));

    // ---- per-point transform ----
    const int m = pid >> 11;
    const float* R  = mrot + m * 9;
    const float* pt = mpoints  + pid * 3;
    const float* nv = mnormals + pid * 3;
    float px = pt[0], py = pt[1], pz = pt[2];
    float vx = nv[0], vy = nv[1], vz = nv[2];
    float r00 = R[0], r01 = R[1], r02 = R[2];
    float r10 = R[3], r11 = R[4], r12 = R[5];
    float r20 = R[6], r21 = R[7], r22 = R[8];
    float tpx = fmaf(r00, px, fmaf(r01, py, r02 * pz)) + mpos[m*3+0];
    float tpy = fmaf(r10, px, fmaf(r11, py, r12 * pz)) + mpos[m*3+1];
    float tpz = fmaf(r20, px, fmaf(r21, py, r22 * pz)) + mpos[m*3+2];
    float tnx = fmaf(r00, vx, fmaf(r01, vy, r02 * vz));
    float tny = fmaf(r10, vx, fmaf(r11, vy, r12 * vz));
    float tnz = fmaf(r20, vx, fmaf(r21, vy, r22 * vz));

    float Nx = snorm[0], Ny = snorm[1], Nz = snorm[2];
    float tnum = fmaf(spos[0] - tpx, Nx,
                 fmaf(spos[1] - tpy, Ny, (spos[2] - tpz) * Nz));

    // ---- conservative occlusion cull ----
    unsigned mask;
    float dzl = zmn - tpz, dzh = zmx - tpz;
    if (dzl <= 0.01f) {
        mask = (0xFFu << 16) | 0xFFFFu;   // sources not clearly above: keep all
    } else {
        float rdl = __fdividef(1.0f, dzl), rdh = __fdividef(1.0f, dzh);
        float nxl = xmn - tpx, nxh = xmx - tpx;
        float nyl = ymn - tpy, nyh = ymx - tpy;
        float wxl = fminf(fminf(nxl*rdl, nxl*rdh) - 1e-4f, 0.f);
        float wxh = fmaxf(fmaxf(nxh*rdl, nxh*rdh) + 1e-4f, 0.f);
        float wyl = fminf(fminf(nyl*rdl, nyl*rdh) - 1e-4f, 0.f);
        float wyh = fmaxf(fmaxf(nyh*rdl, nyh*rdh) + 1e-4f, 0.f);
        mask = 0u;
        #pragma unroll
        for (int c = 0; c < NCYL; c++) {
            float c1x = cp1[3*c], c1y = cp1[3*c+1], c1z = cp1[3*c+2];
            float c2z = cp2[3*c+2];
            float r   = crad[c];
            float dmax = fmaxf(c1z, c2z) - tpz + MARG;
            float Xl = fmaf(dmax, wxl, tpx), Xh = fmaf(dmax, wxh, tpx);
            float Yl = fmaf(dmax, wyl, tpy), Yh = fmaf(dmax, wyh, tpy);
            float ddx = fmaxf(fmaxf(c1x - Xh, Xl - c1x), 0.f);
            float ddy = fmaxf(fmaxf(c1y - Yh, Yl - c1y), 0.f);
            float rr = r + MARG;
            if ((dmax > 0.f) & (fmaf(ddx, ddx, ddy*ddy) <= rr*rr)) mask |= (1u << c);
        }
        #pragma unroll
        for (int b = 0; b < NBOX; b++) {
            float b1x = bp1[3*b], b1y = bp1[3*b+1];
            float b2x = bp2[3*b], b2y = bp2[3*b+1], b2z = bp2[3*b+2];
            float d2 = b2z - tpz + MARG;
            float Xl = fmaf(d2, wxl, tpx), Xh = fmaf(d2, wxh, tpx);
            float Yl = fmaf(d2, wyl, tpy), Yh = fmaf(d2, wyh, tpy);
            bool act = (d2 > 0.f) & (Xh >= b1x - MARG) & (Xl <= b2x + MARG)
                                  & (Yh >= b1y - MARG) & (Yl <= b2y + MARG);
            if (act) mask |= (1u << (16 + b));
        }
    }

    g_tp[pid] = make_float4(tpx, tpy, tpz, __uint_as_float(mask));
    g_tn[pid] = make_float4(tnx, tny, tnz, tnum);
}

__global__ __launch_bounds__(NS) void render_kernel(
    const float* __restrict__ src,
    const float* __restrict__ snorm,
    float* __restrict__ out)
{
    const int pid = blockIdx.x;
    const int tid = threadIdx.x;

    float4 tp4 = g_tp[pid];
    float4 tn4 = g_tn[pid];
    unsigned mask = __float_as_uint(tp4.w);
    unsigned cm = mask & 0xFFFFu;
    unsigned bm = mask >> 16;
    float tpx = tp4.x, tpy = tp4.y, tpz = tp4.z;

    float sx = src[tid*3], sy = src[tid*3+1], sz = src[tid*3+2];
    // unnormalized occlusion direction (mirror point -> source); all hit
    // predicates below are scale-invariant in u.
    float ux = sx - tpx, uy = sy - tpy, uz = sz - tpz;
    float A = fmaf(ux, ux, uy * uy);     // |u_perp|^2 (vertical cylinder axes)

    bool blocked = false;
    while (cm) {
        int c = __ffs(cm) - 1; cm &= cm - 1;
        float4 cg = g_cyl[c];
        float mx = tpx - cg.x, my = tpy - cg.y;
        float hB = fmaf(ux, mx, uy * my);
        float C  = fmaf(mx, mx, fmaf(my, my, -cg.z));
        float dp = fmaf(hB, hB, -A * C);
        if (dp > 0.0f) {
            float L  = g_cylL[c];
            float oa = tpz - cg.w;
            float sq  = sqrt_approx(dp);
            float inv = __fdividef(1.0f, fmaf(2.0f, A, EPSF));
            float t1  = (-2.0f * hB - 2.0f * sq) * inv;
            float t2  = (-2.0f * hB + 2.0f * sq) * inv;
            float x1  = fmaf(t1, uz, oa);
            float x2  = fmaf(t2, uz, oa);
            bool h1 = (t1 > EPSF) & (x1 >= 0.0f) & (x1 <= L);
            bool h2 = (t2 > EPSF) & (x2 >= 0.0f) & (x2 <= L);
            if (h1 | h2) { blocked = true; break; }
        }
    }

    if (bm && !blocked) {
        float aux = (fabsf(ux) < EPSF) ? EPSF : ux;
        float auy = (fabsf(uy) < EPSF) ? EPSF : uy;
        float auz = (fabsf(uz) < EPSF) ? EPSF : uz;
        float ivx = __fdividef(1.0f, aux);
        float ivy = __fdividef(1.0f, auy);
        float ivz = __fdividef(1.0f, auz);
        unsigned b2 = bm;
        while (b2) {
            int b = __ffs(b2) - 1; b2 &= b2 - 1;
            float4 v1 = g_bx1[b];
            float4 v2 = g_bx2[b];
            float lx = (v1.x - tpx) * ivx, hx = (v2.x - tpx) * ivx;
            float ly = (v1.y - tpy) * ivy, hy = (v2.y - tpy) * ivy;
            float lz = (v1.z - tpz) * ivz, hz = (v2.z - tpz) * ivz;
            float nx_ = fminf(lx, hx), xx_ = fmaxf(lx, hx);
            float ny_ = fminf(ly, hy), xy_ = fmaxf(ly, hy);
            float nz_ = fminf(lz, hz), xz_ = fmaxf(lz, hz);
            float tmin = fmaxf(fmaxf(nx_, ny_), nz_);
            float tmax = fminf(fminf(xx_, xy_), xz_);
            if (tmax >= fmaxf(tmin, EPSF)) { blocked = true; break; }
        }
    }

    if (!blocked) {
        // d = -u/|u|.  refl0 = |u| * refl = -u + 2*(u.n)*n ;  q is invariant
        // to the positive scale of refl0.
        float un  = fmaf(ux, tn4.x, fmaf(uy, tn4.y, uz * tn4.z));
        float r0x = fmaf(2.0f * un, tn4.x, -ux);
        float r0y = fmaf(2.0f * un, tn4.y, -uy);
        float r0z = fmaf(2.0f * un, tn4.z, -uz);
        float Nx = snorm[0], Ny = snorm[1], Nz = snorm[2];
        float denom = fmaf(r0x, Nx, fmaf(r0y, Ny, r0z * Nz)) + EPSF;
        float t  = tn4.w * rcp_refined(denom);
        float qx = fmaf(t, r0x, tpx);
        float qy = fmaf(t, r0y, tpy);
        float len2 = fmaf(uz, uz, A);
        float il   = rsqrt_refined(len2);
        float cosv = fabsf(un) * il;
        const float K = (float)IW / (2.0f * EXT);      // 512/24
        float fx = fmaf(qx, K, 0.5f * (float)IW);
        float fy = fmaf(qy, K, 0.5f * (float)IH);
        float flx = floorf(fx), fly = floorf(fy);
        if (flx >= 0.0f && flx < (float)IW && fly >= 0.0f && fly < (float)IH) {
            int ix = (int)flx;
            int iy = (int)fly;
            atomicAdd(out + iy * IW + ix, cosv);
        }
    }
}

extern "C" void kernel_launch(void* const* d_in, const int* in_sizes, int n_in,
                              void* d_out, int out_size) {
    float* out = (float*)d_out;
    prep_kernel<<<NPTS / 128, 128>>>(
        (const float*)d_in[0],   // sources
        (const float*)d_in[1],   // mirror_points
        (const float*)d_in[2],   // mirror_normals
        (const float*)d_in[3],   // mirror_positions
        (const float*)d_in[4],   // mirror_rotations
        (const float*)d_in[5],   // cyl_p1
        (const float*)d_in[6],   // cyl_p2
        (const float*)d_in[7],   // cyl_radius
        (const float*)d_in[8],   // box_p1
        (const float*)d_in[9],   // box_p2
        (const float*)d_in[10],  // sensor_plane_pos
        (const float*)d_in[11],  // sensor_plane_normal
        (float4*)out);
    render_kernel<<<NM * NP, NS>>>(
        (const float*)d_in[0],   // sources
        (const float*)d_in[11],  // sensor_plane_normal
        out);
}

// round 4
// speedup vs baseline: 4.7290x; 1.3414x over previous
#include <cuda_runtime.h>

#define NS 128    // sources (== threads per block)
#define NP 2048   // points per mirror
#define NM 64     // mirrors
#define NPTS (NM*NP)
#define NCYL 16
#define NBOX 8
#define IH 512
#define IW 512
#define NPIX (IH*IW)
#define NREP 16
#define EXT 12.0f
#define EPSF 1e-9f
#define MARG 0.02f

// per-point scratch (written by prep_kernel, read by render_kernel)
__device__ float4 g_tp[NPTS];      // tpx, tpy, tpz, cull-mask (bits0-15 cyl, 16-23 box)
__device__ float4 g_tn[NPTS];      // tnx, tny, tnz, tnum
__device__ float4 g_cyl[NCYL];     // c1x, c1y, r^2, c1z
__device__ float  g_cylL[NCYL];    // axis length
__device__ float4 g_bx1[NBOX];     // box p1
__device__ float4 g_bx2[NBOX];     // box p2
__device__ float  g_img[NREP * NPIX];   // privatized accumulation images (16 MB)

__device__ __forceinline__ float sqrt_approx(float x) {
    float r; asm("sqrt.approx.f32 %0, %1;" : "=f"(r) : "f"(x)); return r;
}
__device__ __forceinline__ float rcp_approx(float x) {
    float r; asm("rcp.approx.f32 %0, %1;" : "=f"(r) : "f"(x)); return r;
}
__device__ __forceinline__ float rcp_refined(float x) {
    float r = rcp_approx(x);
    r = r * (2.0f - x * r);
    return r;
}
__device__ __forceinline__ float rsqrt_refined(float x) {
    float r = rsqrtf(x);
    r = r * fmaf(-0.5f * x * r, r, 1.5f);
    return r;
}

// One thread per mirror point. Also zero-fills the replica images and builds
// the packed geometry tables.
__global__ __launch_bounds__(128) void prep_kernel(
    const float* __restrict__ src,
    const float* __restrict__ mpoints,
    const float* __restrict__ mnormals,
    const float* __restrict__ mpos,
    const float* __restrict__ mrot,
    const float* __restrict__ cp1,
    const float* __restrict__ cp2,
    const float* __restrict__ crad,
    const float* __restrict__ bp1,
    const float* __restrict__ bp2,
    const float* __restrict__ spos,
    const float* __restrict__ snorm)
{
    const int tid = threadIdx.x;
    const int pid = blockIdx.x * 128 + tid;

    // zero the replica images: NREP*NPIX/4 float4s over NPTS threads
    {
        float4* img4 = (float4*)g_img;
        const int tot4 = NREP * NPIX / 4;
        #pragma unroll
        for (int i = pid; i < tot4; i += NPTS)
            img4[i] = make_float4(0.f, 0.f, 0.f, 0.f);
    }

    // geometry tables (block 0 only)
    if (blockIdx.x == 0) {
        if (tid < NCYL) {
            float r = crad[tid];
            g_cyl[tid]  = make_float4(cp1[3*tid], cp1[3*tid+1], r * r, cp1[3*tid+2]);
            g_cylL[tid] = fabsf(cp2[3*tid+2] - cp1[3*tid+2]);
        } else if (tid < NCYL + NBOX) {
            int b = tid - NCYL;
            g_bx1[b] = make_float4(bp1[3*b], bp1[3*b+1], bp1[3*b+2], 0.f);
            g_bx2[b] = make_float4(bp2[3*b], bp2[3*b+1], bp2[3*b+2], 0.f);
        }
    }

    // ---- block-local source-bounds reduction (128 sources, one per thread) ----
    float x = src[tid*3], y = src[tid*3+1], z = src[tid*3+2];
    float xmn = x, xmx = x, ymn = y, ymx = y, zmn = z, zmx = z;
    #pragma unroll
    for (int o = 16; o; o >>= 1) {
        xmn = fminf(xmn, __shfl_xor_sync(0xffffffffu, xmn, o));
        xmx = fmaxf(xmx, __shfl_xor_sync(0xffffffffu, xmx, o));
        ymn = fminf(ymn, __shfl_xor_sync(0xffffffffu, ymn, o));
        ymx = fmaxf(ymx, __shfl_xor_sync(0xffffffffu, ymx, o));
        zmn = fminf(zmn, __shfl_xor_sync(0xffffffffu, zmn, o));
        zmx = fmaxf(zmx, __shfl_xor_sync(0xffffffffu, zmx, o));
    }
    __shared__ float sh[4][6];
    int w = tid >> 5;
    if ((tid & 31) == 0) {
        sh[w][0] = xmn; sh[w][1] = xmx; sh[w][2] = ymn;
        sh[w][3] = ymx; sh[w][4] = zmn; sh[w][5] = zmx;
    }
    __syncthreads();
    xmn = fminf(fminf(sh[0][0], sh[1][0]), fminf(sh[2][0], sh[3][0]));
    xmx = fmaxf(fmaxf(sh[0][1], sh[1][1]), fmaxf(sh[2][1], sh[3][1]));
    ymn = fminf(fminf(sh[0][2], sh[1][2]), fminf(sh[2][2], sh[3][2]));
    ymx = fmaxf(fmaxf(sh[0][3], sh[1][3]), fmaxf(sh[2][3], sh[3][3]));
    zmn = fminf(fminf(sh[0][4], sh[1][4]), fminf(sh[2][4], sh[3][4]));
    zmx = fmaxf(fmaxf(sh[0][5], sh[1][5]), fmaxf(sh[2][5], sh[3][5]));

    // ---- per-point transform ----
    const int m = pid >> 11;
    const float* R  = mrot + m * 9;
    const float* pt = mpoints  + pid * 3;
    const float* nv = mnormals + pid * 3;
    float px = pt[0], py = pt[1], pz = pt[2];
    float vx = nv[0], vy = nv[1], vz = nv[2];
    float r00 = R[0], r01 = R[1], r02 = R[2];
    float r10 = R[3], r11 = R[4], r12 = R[5];
    float r20 = R[6], r21 = R[7], r22 = R[8];
    float tpx = fmaf(r00, px, fmaf(r01, py, r02 * pz)) + mpos[m*3+0];
    float tpy = fmaf(r10, px, fmaf(r11, py, r12 * pz)) + mpos[m*3+1];
    float tpz = fmaf(r20, px, fmaf(r21, py, r22 * pz)) + mpos[m*3+2];
    float tnx = fmaf(r00, vx, fmaf(r01, vy, r02 * vz));
    float tny = fmaf(r10, vx, fmaf(r11, vy, r12 * vz));
    float tnz = fmaf(r20, vx, fmaf(r21, vy, r22 * vz));

    float Nx = snorm[0], Ny = snorm[1], Nz = snorm[2];
    float tnum = fmaf(spos[0] - tpx, Nx,
                 fmaf(spos[1] - tpy, Ny, (spos[2] - tpz) * Nz));

    // ---- conservative occlusion cull ----
    unsigned mask;
    float dzl = zmn - tpz, dzh = zmx - tpz;
    if (dzl <= 0.01f) {
        mask = (0xFFu << 16) | 0xFFFFu;   // sources not clearly above: keep all
    } else {
        float rdl = __fdividef(1.0f, dzl), rdh = __fdividef(1.0f, dzh);
        float nxl = xmn - tpx, nxh = xmx - tpx;
        float nyl = ymn - tpy, nyh = ymx - tpy;
        float wxl = fminf(fminf(nxl*rdl, nxl*rdh) - 1e-4f, 0.f);
        float wxh = fmaxf(fmaxf(nxh*rdl, nxh*rdh) + 1e-4f, 0.f);
        float wyl = fminf(fminf(nyl*rdl, nyl*rdh) - 1e-4f, 0.f);
        float wyh = fmaxf(fmaxf(nyh*rdl, nyh*rdh) + 1e-4f, 0.f);
        mask = 0u;
        #pragma unroll
        for (int c = 0; c < NCYL; c++) {
            float c1x = cp1[3*c], c1y = cp1[3*c+1], c1z = cp1[3*c+2];
            float c2z = cp2[3*c+2];
            float r   = crad[c];
            float dmax = fmaxf(c1z, c2z) - tpz + MARG;
            float Xl = fmaf(dmax, wxl, tpx), Xh = fmaf(dmax, wxh, tpx);
            float Yl = fmaf(dmax, wyl, tpy), Yh = fmaf(dmax, wyh, tpy);
            float ddx = fmaxf(fmaxf(c1x - Xh, Xl - c1x), 0.f);
            float ddy = fmaxf(fmaxf(c1y - Yh, Yl - c1y), 0.f);
            float rr = r + MARG;
            if ((dmax > 0.f) & (fmaf(ddx, ddx, ddy*ddy) <= rr*rr)) mask |= (1u << c);
        }
        #pragma unroll
        for (int b = 0; b < NBOX; b++) {
            float b1x = bp1[3*b], b1y = bp1[3*b+1];
            float b2x = bp2[3*b], b2y = bp2[3*b+1], b2z = bp2[3*b+2];
            float d2 = b2z - tpz + MARG;
            float Xl = fmaf(d2, wxl, tpx), Xh = fmaf(d2, wxh, tpx);
            float Yl = fmaf(d2, wyl, tpy), Yh = fmaf(d2, wyh, tpy);
            bool act = (d2 > 0.f) & (Xh >= b1x - MARG) & (Xl <= b2x + MARG)
                                  & (Yh >= b1y - MARG) & (Yl <= b2y + MARG);
            if (act) mask |= (1u << (16 + b));
        }
    }

    g_tp[pid] = make_float4(tpx, tpy, tpz, __uint_as_float(mask));
    g_tn[pid] = make_float4(tnx, tny, tnz, tnum);
}

// sum the replicas into the output image
__global__ __launch_bounds__(256) void reduce_kernel(float4* __restrict__ out4) {
    int i = blockIdx.x * 256 + threadIdx.x;   // 0 .. NPIX/4-1
    const float4* img4 = (const float4*)g_img;
    float4 a = img4[i];
    #pragma unroll
    for (int r = 1; r < NREP; r++) {
        float4 b = img4[r * (NPIX/4) + i];
        a.x += b.x; a.y += b.y; a.z += b.z; a.w += b.w;
    }
    out4[i] = a;
}

__global__ __launch_bounds__(NS) void render_kernel(
    const float* __restrict__ src,
    const float* __restrict__ snorm)
{
    const int tid = threadIdx.x;

    float sx = src[tid*3], sy = src[tid*3+1], sz = src[tid*3+2];
    float* img = g_img + ((blockIdx.x + tid) & (NREP - 1)) * NPIX;

    #pragma unroll
    for (int jj = 0; jj < 2; jj++) {
        const int pid = blockIdx.x * 2 + jj;

        float4 tp4 = g_tp[pid];
        float4 tn4 = g_tn[pid];
        unsigned mask = __float_as_uint(tp4.w);
        unsigned cm = mask & 0xFFFFu;
        unsigned bm = mask >> 16;
        float tpx = tp4.x, tpy = tp4.y, tpz = tp4.z;

        // unnormalized occlusion direction (mirror point -> source)
        float ux = sx - tpx, uy = sy - tpy, uz = sz - tpz;
        float A = fmaf(ux, ux, uy * uy);     // |u_perp|^2 (vertical axes)

        bool blocked = false;
        while (cm) {
            int c = __ffs(cm) - 1; cm &= cm - 1;
            float4 cg = g_cyl[c];
            float mx = tpx - cg.x, my = tpy - cg.y;
            float hB = fmaf(ux, mx, uy * my);
            float C  = fmaf(mx, mx, fmaf(my, my, -cg.z));
            float dp = fmaf(hB, hB, -A * C);
            if (dp > 0.0f) {
                float L  = g_cylL[c];
                float oa = tpz - cg.w;
                float sq  = sqrt_approx(dp);
                float inv = __fdividef(1.0f, fmaf(2.0f, A, EPSF));
                float t1  = (-2.0f * hB - 2.0f * sq) * inv;
                float t2  = (-2.0f * hB + 2.0f * sq) * inv;
                float x1  = fmaf(t1, uz, oa);
                float x2  = fmaf(t2, uz, oa);
                bool h1 = (t1 > EPSF) & (x1 >= 0.0f) & (x1 <= L);
                bool h2 = (t2 > EPSF) & (x2 >= 0.0f) & (x2 <= L);
                if (h1 | h2) { blocked = true; break; }
            }
        }

        if (bm && !blocked) {
            float aux = (fabsf(ux) < EPSF) ? EPSF : ux;
            float auy = (fabsf(uy) < EPSF) ? EPSF : uy;
            float auz = (fabsf(uz) < EPSF) ? EPSF : uz;
            float ivx = __fdividef(1.0f, aux);
            float ivy = __fdividef(1.0f, auy);
            float ivz = __fdividef(1.0f, auz);
            unsigned b2 = bm;
            while (b2) {
                int b = __ffs(b2) - 1; b2 &= b2 - 1;
                float4 v1 = g_bx1[b];
                float4 v2 = g_bx2[b];
                float lx = (v1.x - tpx) * ivx, hx = (v2.x - tpx) * ivx;
                float ly = (v1.y - tpy) * ivy, hy = (v2.y - tpy) * ivy;
                float lz = (v1.z - tpz) * ivz, hz = (v2.z - tpz) * ivz;
                float nx_ = fminf(lx, hx), xx_ = fmaxf(lx, hx);
                float ny_ = fminf(ly, hy), xy_ = fmaxf(ly, hy);
                float nz_ = fminf(lz, hz), xz_ = fmaxf(lz, hz);
                float tmin = fmaxf(fmaxf(nx_, ny_), nz_);
                float tmax = fminf(fminf(xx_, xy_), xz_);
                if (tmax >= fmaxf(tmin, EPSF)) { blocked = true; break; }
            }
        }

        if (!blocked) {
            float un  = fmaf(ux, tn4.x, fmaf(uy, tn4.y, uz * tn4.z));
            float r0x = fmaf(2.0f * un, tn4.x, -ux);
            float r0y = fmaf(2.0f * un, tn4.y, -uy);
            float r0z = fmaf(2.0f * un, tn4.z, -uz);
            float Nx = snorm[0], Ny = snorm[1], Nz = snorm[2];
            float denom = fmaf(r0x, Nx, fmaf(r0y, Ny, r0z * Nz)) + EPSF;
            float t  = tn4.w * rcp_refined(denom);
            float qx = fmaf(t, r0x, tpx);
            float qy = fmaf(t, r0y, tpy);
            float len2 = fmaf(uz, uz, A);
            float il   = rsqrt_refined(len2);
            float cosv = fabsf(un) * il;
            const float K = (float)IW / (2.0f * EXT);
            float fx = fmaf(qx, K, 0.5f * (float)IW);
            float fy = fmaf(qy, K, 0.5f * (float)IH);
            float flx = floorf(fx), fly = floorf(fy);
            if (flx >= 0.0f && flx < (float)IW && fly >= 0.0f && fly < (float)IH) {
                int ix = (int)flx;
                int iy = (int)fly;
                atomicAdd(img + iy * IW + ix, cosv);
            }
        }
    }
}

extern "C" void kernel_launch(void* const* d_in, const int* in_sizes, int n_in,
                              void* d_out, int out_size) {
    float* out = (float*)d_out;
    prep_kernel<<<NPTS / 128, 128>>>(
        (const float*)d_in[0],   // sources
        (const float*)d_in[1],   // mirror_points
        (const float*)d_in[2],   // mirror_normals
        (const float*)d_in[3],   // mirror_positions
        (const float*)d_in[4],   // mirror_rotations
        (const float*)d_in[5],   // cyl_p1
        (const float*)d_in[6],   // cyl_p2
        (const float*)d_in[7],   // cyl_radius
        (const float*)d_in[8],   // box_p1
        (const float*)d_in[9],   // box_p2
        (const float*)d_in[10],  // sensor_plane_pos
        (const float*)d_in[11]); // sensor_plane_normal
    render_kernel<<<NPTS / 2, NS>>>(
        (const float*)d_in[0],   // sources
        (const float*)d_in[11]); // sensor_plane_normal
    reduce_kernel<<<NPIX / 4 / 256, 256>>>((float4*)out);
}